// round 2
// baseline (speedup 1.0000x reference)
#include <cuda_runtime.h>
#include <cuda_fp16.h>
#include <cstdint>

// ============================================================================
// Problem sizes (fixed for this dataset)
// ============================================================================
static constexpr int DIMN  = 4096;
static constexpr int HID   = 11008;
static constexpr int MROWS = 8192;   // B*S = 4*2048

// ============================================================================
// Device scratch (allocation-free rule: __device__ globals)
// ============================================================================
static __device__ __align__(256) __half g_x  [(size_t)MROWS * DIMN];
static __device__ __align__(256) __half g_wg [(size_t)HID   * DIMN];
static __device__ __align__(256) __half g_wu [(size_t)HID   * DIMN];
static __device__ __align__(256) __half g_wd [(size_t)DIMN  * HID ];
static __device__ __align__(256) __half g_mid[(size_t)MROWS * HID ];

// ============================================================================
// PTX helpers — ONLY compute_103-safe instructions (no tcgen05/"a" features):
// cp.async (sm_80), ldmatrix (sm_75), mma.sync.m16n8k16 (sm_80)
// ============================================================================
__device__ __forceinline__ uint32_t smem_to_u32(const void* smem_ptr) {
    uint32_t addr;
    asm("{ .reg .u64 tmp; cvta.to.shared.u64 tmp, %1; cvt.u32.u64 %0, tmp; }"
        : "=r"(addr) : "l"(smem_ptr));
    return addr;
}

__device__ __forceinline__ void cp_async16(uint32_t dst, const void* src) {
    asm volatile("cp.async.cg.shared.global [%0], [%1], 16;\n"
                 :: "r"(dst), "l"(src) : "memory");
}
#define CP_COMMIT() asm volatile("cp.async.commit_group;\n" ::: "memory")
template <int N>
__device__ __forceinline__ void cp_wait() {
    asm volatile("cp.async.wait_group %0;\n" :: "n"(N) : "memory");
}

__device__ __forceinline__ void ldsm_x4(uint32_t& r0, uint32_t& r1,
                                        uint32_t& r2, uint32_t& r3, uint32_t addr) {
    asm volatile("ldmatrix.sync.aligned.m8n8.x4.shared.b16 {%0,%1,%2,%3}, [%4];"
                 : "=r"(r0), "=r"(r1), "=r"(r2), "=r"(r3) : "r"(addr));
}

__device__ __forceinline__ void mma16816(float* c, const uint32_t* a, const uint32_t* b) {
    asm volatile(
        "mma.sync.aligned.m16n8k16.row.col.f32.f16.f16.f32 "
        "{%0,%1,%2,%3}, {%4,%5,%6,%7}, {%8,%9}, {%0,%1,%2,%3};"
        : "+f"(c[0]), "+f"(c[1]), "+f"(c[2]), "+f"(c[3])
        : "r"(a[0]), "r"(a[1]), "r"(a[2]), "r"(a[3]), "r"(b[0]), "r"(b[1]));
}

// ============================================================================
// Dequant / convert kernels (memory bound, ~150us total)
// ============================================================================
__global__ void cvt_i32_to_h(const int4* __restrict__ w, uint4* __restrict__ o, int n8) {
    int i = blockIdx.x * blockDim.x + threadIdx.x;
    if (i >= n8) return;
    int4 a = w[2 * i];
    int4 b = w[2 * i + 1];
    __half2 h0 = __halves2half2(__int2half_rn(a.x), __int2half_rn(a.y));
    __half2 h1 = __halves2half2(__int2half_rn(a.z), __int2half_rn(a.w));
    __half2 h2 = __halves2half2(__int2half_rn(b.x), __int2half_rn(b.y));
    __half2 h3 = __halves2half2(__int2half_rn(b.z), __int2half_rn(b.w));
    uint4 r;
    r.x = *reinterpret_cast<uint32_t*>(&h0);
    r.y = *reinterpret_cast<uint32_t*>(&h1);
    r.z = *reinterpret_cast<uint32_t*>(&h2);
    r.w = *reinterpret_cast<uint32_t*>(&h3);
    o[i] = r;
}

__global__ void cvt_f32_to_h(const float4* __restrict__ x, uint4* __restrict__ o, int n8) {
    int i = blockIdx.x * blockDim.x + threadIdx.x;
    if (i >= n8) return;
    float4 a = x[2 * i];
    float4 b = x[2 * i + 1];
    __half2 h0 = __floats2half2_rn(a.x, a.y);
    __half2 h1 = __floats2half2_rn(a.z, a.w);
    __half2 h2 = __floats2half2_rn(b.x, b.y);
    __half2 h3 = __floats2half2_rn(b.z, b.w);
    uint4 r;
    r.x = *reinterpret_cast<uint32_t*>(&h0);
    r.y = *reinterpret_cast<uint32_t*>(&h1);
    r.z = *reinterpret_cast<uint32_t*>(&h2);
    r.w = *reinterpret_cast<uint32_t*>(&h3);
    o[i] = r;
}

// ============================================================================
// Multistage cp.async + mma.sync GEMM (C = A * B^T), fp16 in, fp32 accum.
//   NB==2: two B matrices (gate/up) share the A tile; SwiGLU fused epilogue
//          writes fp16 mid. Tile: 128 x 64 (per matrix) x 64k.
//   NB==1: single B (down proj); scaled fp32 epilogue. Tile: 128 x 128 x 64k.
// 256 threads = 8 warps in a 4(m) x 2(n) grid; warp tile 32 x (BN_EACH/2).
// SMEM rows are 64 halves = 128B, XOR-swizzled: chunk(bits 4-6) ^= row%8.
// ============================================================================
template <int NB, int STAGES>
__global__ void __launch_bounds__(256, 1) ffn_gemm(
    const __half* __restrict__ A,
    const __half* __restrict__ B0,
    const __half* __restrict__ B1,
    void* __restrict__ outp,
    const float* __restrict__ s0p,
    const float* __restrict__ s1p,
    int K, int ntiles, int ncols)
{
    constexpr int BM = 128, BK = 64;
    constexpr int BN_EACH = (NB == 2) ? 64 : 128;
    constexpr int NMMA = BN_EACH / 2 / 8;          // n8 mmas per warp per matrix: 4 or 8
    constexpr int A_BYTES = BM * BK * 2;           // 16384
    constexpr int B_BYTES = BN_EACH * BK * 2;      // 8192 or 16384
    constexpr int STAGE_BYTES = A_BYTES + NB * B_BYTES;   // 32768 either way

    extern __shared__ char smem[];
    const uint32_t sb = smem_to_u32(smem);

    const int tid  = threadIdx.x;
    const int wid  = tid >> 5;
    const int lane = tid & 31;
    const int wm   = wid >> 1;      // 0..3
    const int wn   = wid & 1;       // 0..1
    const int quad = lane >> 3;     // 0..3 (ldmatrix sub-matrix)
    const int qr   = lane & 7;

    // L2-friendly tile mapping: groups of 8 m-tiles, n fastest within a group
    constexpr int GM = 8;
    const int tpg = GM * ntiles;
    const int grp = blockIdx.x / tpg;
    const int rem = blockIdx.x % tpg;
    const int mt  = grp * GM + (rem % GM);
    const int nt  = rem / GM;

    const int kch = K / BK;

    float acc[NB][2][NMMA][4];
#pragma unroll
    for (int g = 0; g < NB; g++)
#pragma unroll
        for (int mi = 0; mi < 2; mi++)
#pragma unroll
            for (int ni = 0; ni < NMMA; ni++)
#pragma unroll
                for (int q = 0; q < 4; q++) acc[g][mi][ni][q] = 0.f;

    const __half* aT = A + (size_t)(mt * BM) * K;
    const __half* bT[2];
    bT[0] = B0 + (size_t)(nt * BN_EACH) * K;
    bT[1] = B1 + (size_t)(nt * BN_EACH) * K;

    // ---- stage loader: 16B chunks, swizzled smem, coalesced global reads ----
    auto load_stage = [&](int kc, int slot) {
        const uint32_t st = sb + slot * STAGE_BYTES;
        const int k0 = kc * BK;
#pragma unroll
        for (int it = 0; it < (BM * 8) / 256; it++) {
            int id = it * 256 + tid;
            int row = id >> 3, ch = id & 7;
            uint32_t dst = st + row * 128 + ((ch * 16) ^ ((row & 7) << 4));
            cp_async16(dst, aT + (size_t)row * K + k0 + ch * 8);
        }
#pragma unroll
        for (int g = 0; g < NB; g++) {
            const __half* bp = bT[g];
            const uint32_t bbase = st + A_BYTES + g * B_BYTES;
#pragma unroll
            for (int it = 0; it < (BN_EACH * 8) / 256; it++) {
                int id = it * 256 + tid;
                int row = id >> 3, ch = id & 7;
                uint32_t dst = bbase + row * 128 + ((ch * 16) ^ ((row & 7) << 4));
                cp_async16(dst, bp + (size_t)row * K + k0 + ch * 8);
            }
        }
    };

    // ---- prologue ----
#pragma unroll
    for (int s = 0; s < STAGES - 1; s++) {
        if (s < kch) load_stage(s, s);
        CP_COMMIT();
    }

    // ---- main loop ----
    for (int kc = 0; kc < kch; kc++) {
        const int pre = kc + STAGES - 1;
        if (pre < kch) load_stage(pre, pre % STAGES);
        CP_COMMIT();
        cp_wait<STAGES - 2>();
        __syncthreads();

        const uint32_t st = sb + (kc % STAGES) * STAGE_BYTES;
#pragma unroll
        for (int ks = 0; ks < 4; ks++) {
            // A fragments: two m16 rows of the 32-row warp tile
            uint32_t a[2][4];
#pragma unroll
            for (int mi = 0; mi < 2; mi++) {
                int row  = wm * 32 + mi * 16 + (quad & 1) * 8 + qr;
                int colb = ks * 32 + (quad >> 1) * 16;
                uint32_t ad = st + row * 128 + (colb ^ ((row & 7) << 4));
                ldsm_x4(a[mi][0], a[mi][1], a[mi][2], a[mi][3], ad);
            }
            // B fragments: n16 groups
            uint32_t b[NB][NMMA / 2][4];
#pragma unroll
            for (int g = 0; g < NB; g++)
#pragma unroll
                for (int j = 0; j < NMMA / 2; j++) {
                    int row  = wn * (NMMA * 8) + j * 16 + (quad >> 1) * 8 + qr;
                    int colb = ks * 32 + (quad & 1) * 16;
                    uint32_t bd = st + A_BYTES + g * B_BYTES + row * 128 +
                                  (colb ^ ((row & 7) << 4));
                    ldsm_x4(b[g][j][0], b[g][j][1], b[g][j][2], b[g][j][3], bd);
                }
#pragma unroll
            for (int g = 0; g < NB; g++)
#pragma unroll
                for (int mi = 0; mi < 2; mi++)
#pragma unroll
                    for (int ni = 0; ni < NMMA; ni++)
                        mma16816(acc[g][mi][ni], a[mi], &b[g][ni >> 1][(ni & 1) * 2]);
        }
        __syncthreads();
    }

    // ---- epilogue ----
    const float s0 = *s0p;
    const float s1 = *s1p;
    if (NB == 2) {
        __half* out = (__half*)outp;
#pragma unroll
        for (int mi = 0; mi < 2; mi++)
#pragma unroll
            for (int ni = 0; ni < NMMA; ni++) {
                int row0 = mt * BM + wm * 32 + mi * 16 + (lane >> 2);
                int col  = nt * BN_EACH + wn * (NMMA * 8) + ni * 8 + (lane & 3) * 2;
#pragma unroll
                for (int h = 0; h < 2; h++) {
                    int row = row0 + h * 8;
                    float g0 = s0 * acc[0][mi][ni][2 * h + 0];
                    float g1 = s0 * acc[0][mi][ni][2 * h + 1];
                    float u0 = s1 * acc[1][mi][ni][2 * h + 0];
                    float u1 = s1 * acc[1][mi][ni][2 * h + 1];
                    float r0 = g0 / (1.f + __expf(-g0)) * u0;
                    float r1 = g1 / (1.f + __expf(-g1)) * u1;
                    *(__half2*)(out + (size_t)row * ncols + col) =
                        __floats2half2_rn(r0, r1);
                }
            }
    } else {
        float* out = (float*)outp;
#pragma unroll
        for (int mi = 0; mi < 2; mi++)
#pragma unroll
            for (int ni = 0; ni < NMMA; ni++) {
                int row0 = mt * BM + wm * 32 + mi * 16 + (lane >> 2);
                int col  = nt * BN_EACH + wn * (NMMA * 8) + ni * 8 + (lane & 3) * 2;
#pragma unroll
                for (int h = 0; h < 2; h++) {
                    int row = row0 + h * 8;
                    float2 v;
                    v.x = s0 * acc[0][mi][ni][2 * h + 0];
                    v.y = s0 * acc[0][mi][ni][2 * h + 1];
                    *(float2*)(out + (size_t)row * ncols + col) = v;
                }
            }
    }
}

// ============================================================================
// Host side
// ============================================================================
extern "C" void kernel_launch(void* const* d_in, const int* in_sizes, int n_in,
                              void* d_out, int out_size) {
    const float* x  = (const float*)d_in[0];
    const int*   wg = (const int*)d_in[1];
    const int*   wu = (const int*)d_in[2];
    const int*   wd = (const int*)d_in[3];
    const float* sg = (const float*)d_in[4];
    const float* su = (const float*)d_in[5];
    const float* sd = (const float*)d_in[6];

    void *px, *pwg, *pwu, *pwd, *pmid;
    cudaGetSymbolAddress(&px,  g_x);
    cudaGetSymbolAddress(&pwg, g_wg);
    cudaGetSymbolAddress(&pwu, g_wu);
    cudaGetSymbolAddress(&pwd, g_wd);
    cudaGetSymbolAddress(&pmid, g_mid);

    // --- dequant / convert ---
    {
        int n8x = (MROWS * DIMN) / 8;
        cvt_f32_to_h<<<n8x / 256, 256>>>((const float4*)x, (uint4*)px, n8x);
        int n8w = (HID * DIMN) / 8;
        cvt_i32_to_h<<<n8w / 256, 256>>>((const int4*)wg, (uint4*)pwg, n8w);
        cvt_i32_to_h<<<n8w / 256, 256>>>((const int4*)wu, (uint4*)pwu, n8w);
        cvt_i32_to_h<<<n8w / 256, 256>>>((const int4*)wd, (uint4*)pwd, n8w);
    }

    constexpr int STAGES = 6;
    constexpr int SMEM_BYTES = STAGES * 32768;   // 196608
    cudaFuncSetAttribute(ffn_gemm<2, STAGES>,
                         cudaFuncAttributeMaxDynamicSharedMemorySize, SMEM_BYTES);
    cudaFuncSetAttribute(ffn_gemm<1, STAGES>,
                         cudaFuncAttributeMaxDynamicSharedMemorySize, SMEM_BYTES);

    // GEMM1: fused gate+up+SwiGLU -> g_mid (fp16).  C tiles: 128x64 (x2 mats)
    {
        int mtiles = MROWS / 128;   // 64
        int ntiles = HID / 64;      // 172
        ffn_gemm<2, STAGES><<<mtiles * ntiles, 256, SMEM_BYTES>>>(
            (const __half*)px, (const __half*)pwg, (const __half*)pwu,
            pmid, sg, su, DIMN, ntiles, HID);
    }
    // GEMM2: down projection -> d_out (fp32).  C tiles: 128x128
    {
        int mtiles = MROWS / 128;   // 64
        int ntiles = DIMN / 128;    // 32
        ffn_gemm<1, STAGES><<<mtiles * ntiles, 256, SMEM_BYTES>>>(
            (const __half*)pmid, (const __half*)pwd, (const __half*)pwd,
            d_out, sd, sd, HID, ntiles, DIMN);
    }
}

// round 3
// speedup vs baseline: 1.2238x; 1.2238x over previous
#include <cuda_runtime.h>
#include <cuda_fp16.h>
#include <cstdint>

// ============================================================================
// Problem sizes (fixed for this dataset)
// ============================================================================
static constexpr int DIMN  = 4096;
static constexpr int HID   = 11008;
static constexpr int MROWS = 8192;   // B*S = 4*2048

// ============================================================================
// Device scratch (allocation-free rule: __device__ globals)
// ============================================================================
static __device__ __align__(256) __half g_x  [(size_t)MROWS * DIMN];
static __device__ __align__(256) __half g_wg [(size_t)HID   * DIMN];
static __device__ __align__(256) __half g_wu [(size_t)HID   * DIMN];
static __device__ __align__(256) __half g_wd [(size_t)DIMN  * HID ];
static __device__ __align__(256) __half g_mid[(size_t)MROWS * HID ];

// ============================================================================
// PTX helpers — compute_103-safe only (cp.async, ldmatrix, mma.sync.m16n8k16)
// ============================================================================
__device__ __forceinline__ uint32_t smem_to_u32(const void* smem_ptr) {
    uint32_t addr;
    asm("{ .reg .u64 tmp; cvta.to.shared.u64 tmp, %1; cvt.u32.u64 %0, tmp; }"
        : "=r"(addr) : "l"(smem_ptr));
    return addr;
}

__device__ __forceinline__ void cp_async16(uint32_t dst, const void* src) {
    asm volatile("cp.async.cg.shared.global [%0], [%1], 16;\n"
                 :: "r"(dst), "l"(src) : "memory");
}
#define CP_COMMIT() asm volatile("cp.async.commit_group;\n" ::: "memory")
template <int N>
__device__ __forceinline__ void cp_wait() {
    asm volatile("cp.async.wait_group %0;\n" :: "n"(N) : "memory");
}

__device__ __forceinline__ void ldsm_x4(uint32_t& r0, uint32_t& r1,
                                        uint32_t& r2, uint32_t& r3, uint32_t addr) {
    asm volatile("ldmatrix.sync.aligned.m8n8.x4.shared.b16 {%0,%1,%2,%3}, [%4];"
                 : "=r"(r0), "=r"(r1), "=r"(r2), "=r"(r3) : "r"(addr));
}

__device__ __forceinline__ void mma16816(float* c, const uint32_t* a, const uint32_t* b) {
    asm volatile(
        "mma.sync.aligned.m16n8k16.row.col.f32.f16.f16.f32 "
        "{%0,%1,%2,%3}, {%4,%5,%6,%7}, {%8,%9}, {%0,%1,%2,%3};"
        : "+f"(c[0]), "+f"(c[1]), "+f"(c[2]), "+f"(c[3])
        : "r"(a[0]), "r"(a[1]), "r"(a[2]), "r"(a[3]), "r"(b[0]), "r"(b[1]));
}

// ============================================================================
// Dequant / convert kernels (memory bound, ~150us total)
// ============================================================================
__global__ void cvt_i32_to_h(const int4* __restrict__ w, uint4* __restrict__ o, int n8) {
    int i = blockIdx.x * blockDim.x + threadIdx.x;
    if (i >= n8) return;
    int4 a = w[2 * i];
    int4 b = w[2 * i + 1];
    __half2 h0 = __halves2half2(__int2half_rn(a.x), __int2half_rn(a.y));
    __half2 h1 = __halves2half2(__int2half_rn(a.z), __int2half_rn(a.w));
    __half2 h2 = __halves2half2(__int2half_rn(b.x), __int2half_rn(b.y));
    __half2 h3 = __halves2half2(__int2half_rn(b.z), __int2half_rn(b.w));
    uint4 r;
    r.x = *reinterpret_cast<uint32_t*>(&h0);
    r.y = *reinterpret_cast<uint32_t*>(&h1);
    r.z = *reinterpret_cast<uint32_t*>(&h2);
    r.w = *reinterpret_cast<uint32_t*>(&h3);
    o[i] = r;
}

__global__ void cvt_f32_to_h(const float4* __restrict__ x, uint4* __restrict__ o, int n8) {
    int i = blockIdx.x * blockDim.x + threadIdx.x;
    if (i >= n8) return;
    float4 a = x[2 * i];
    float4 b = x[2 * i + 1];
    __half2 h0 = __floats2half2_rn(a.x, a.y);
    __half2 h1 = __floats2half2_rn(a.z, a.w);
    __half2 h2 = __floats2half2_rn(b.x, b.y);
    __half2 h3 = __floats2half2_rn(b.z, b.w);
    uint4 r;
    r.x = *reinterpret_cast<uint32_t*>(&h0);
    r.y = *reinterpret_cast<uint32_t*>(&h1);
    r.z = *reinterpret_cast<uint32_t*>(&h2);
    r.w = *reinterpret_cast<uint32_t*>(&h3);
    o[i] = r;
}

// ============================================================================
// Multistage cp.async + mma.sync GEMM (C = A * B^T), fp16 in, fp32 accum.
//   NB==2 (BN_EACH=128): gate+up share A tile; fused SwiGLU -> fp16 mid.
//   NB==1 (BN_EACH=256): down proj; scaled fp32 out.
// CTA tile: 128(m) x 256(n-total) x 64(k). 256 threads = 8 warps as 2m x 4n;
// warp tile 64m x 64n-total. acc = 128 fp32/thread.
// SMEM rows 64 halves = 128B, XOR-swizzled: byte[6:4] ^= row[2:0].
// ============================================================================
template <int NB, int BN_EACH, int STAGES>
__global__ void __launch_bounds__(256, 1) ffn_gemm(
    const __half* __restrict__ A,
    const __half* __restrict__ B0,
    const __half* __restrict__ B1,
    void* __restrict__ outp,
    const float* __restrict__ s0p,
    const float* __restrict__ s1p,
    int K, int ntiles, int ncols)
{
    constexpr int BM = 128, BK = 64;
    constexpr int WN_COLS = BN_EACH / 4;          // warp n-slice per matrix: 32 or 64
    constexpr int MI   = 4;                        // m16 groups per warp (64 rows)
    constexpr int NMMA = WN_COLS / 8;              // n8 mmas per warp per matrix: 4 or 8
    constexpr int A_BYTES = BM * BK * 2;           // 16384
    constexpr int B_BYTES = BN_EACH * BK * 2;      // 16384 or 32768
    constexpr int STAGE_BYTES = A_BYTES + NB * B_BYTES;   // 49152 either way

    extern __shared__ char smem[];
    const uint32_t sb = smem_to_u32(smem);

    const int tid  = threadIdx.x;
    const int wid  = tid >> 5;
    const int lane = tid & 31;
    const int wm   = wid & 1;       // 0..1 (m)
    const int wn   = wid >> 1;      // 0..3 (n)
    const int quad = lane >> 3;     // 0..3 (ldmatrix sub-matrix)
    const int qr   = lane & 7;

    // L2-friendly tile mapping: groups of 8 m-tiles, n fastest within a group
    constexpr int GM = 8;
    const int tpg = GM * ntiles;
    const int grp = blockIdx.x / tpg;
    const int rem = blockIdx.x % tpg;
    const int mt  = grp * GM + (rem % GM);
    const int nt  = rem / GM;

    const int kch = K / BK;

    float acc[NB][MI][NMMA][4];
#pragma unroll
    for (int g = 0; g < NB; g++)
#pragma unroll
        for (int mi = 0; mi < MI; mi++)
#pragma unroll
            for (int ni = 0; ni < NMMA; ni++)
#pragma unroll
                for (int q = 0; q < 4; q++) acc[g][mi][ni][q] = 0.f;

    const __half* aT = A + (size_t)(mt * BM) * K;
    const __half* bT[2];
    bT[0] = B0 + (size_t)(nt * BN_EACH) * K;
    bT[1] = B1 + (size_t)(nt * BN_EACH) * K;

    // ---- stage loader: 16B chunks, swizzled smem, coalesced global reads ----
    auto load_stage = [&](int kc, int slot) {
        const uint32_t st = sb + slot * STAGE_BYTES;
        const int k0 = kc * BK;
#pragma unroll
        for (int it = 0; it < (BM * 8) / 256; it++) {
            int id = it * 256 + tid;
            int row = id >> 3, ch = id & 7;
            uint32_t dst = st + row * 128 + ((ch * 16) ^ ((row & 7) << 4));
            cp_async16(dst, aT + (size_t)row * K + k0 + ch * 8);
        }
#pragma unroll
        for (int g = 0; g < NB; g++) {
            const __half* bp = bT[g];
            const uint32_t bbase = st + A_BYTES + g * B_BYTES;
#pragma unroll
            for (int it = 0; it < (BN_EACH * 8) / 256; it++) {
                int id = it * 256 + tid;
                int row = id >> 3, ch = id & 7;
                uint32_t dst = bbase + row * 128 + ((ch * 16) ^ ((row & 7) << 4));
                cp_async16(dst, bp + (size_t)row * K + k0 + ch * 8);
            }
        }
    };

    // ---- prologue ----
#pragma unroll
    for (int s = 0; s < STAGES - 1; s++) {
        if (s < kch) load_stage(s, s);
        CP_COMMIT();
    }

    // ---- main loop ----
    for (int kc = 0; kc < kch; kc++) {
        const int pre = kc + STAGES - 1;
        if (pre < kch) load_stage(pre, pre % STAGES);
        CP_COMMIT();
        cp_wait<STAGES - 2>();
        __syncthreads();

        const uint32_t st = sb + (kc % STAGES) * STAGE_BYTES;
#pragma unroll
        for (int ks = 0; ks < 4; ks++) {
            // A fragments: four m16 groups of the 64-row warp tile
            uint32_t a[MI][4];
#pragma unroll
            for (int mi = 0; mi < MI; mi++) {
                int row  = wm * 64 + mi * 16 + (quad & 1) * 8 + qr;
                int colb = ks * 32 + (quad >> 1) * 16;
                uint32_t ad = st + row * 128 + (colb ^ ((row & 7) << 4));
                ldsm_x4(a[mi][0], a[mi][1], a[mi][2], a[mi][3], ad);
            }
            // B fragments: n16 groups per matrix
            uint32_t b[NB][NMMA / 2][4];
#pragma unroll
            for (int g = 0; g < NB; g++)
#pragma unroll
                for (int j = 0; j < NMMA / 2; j++) {
                    int row  = wn * WN_COLS + j * 16 + (quad >> 1) * 8 + qr;
                    int colb = ks * 32 + (quad & 1) * 16;
                    uint32_t bd = st + A_BYTES + g * B_BYTES + row * 128 +
                                  (colb ^ ((row & 7) << 4));
                    ldsm_x4(b[g][j][0], b[g][j][1], b[g][j][2], b[g][j][3], bd);
                }
#pragma unroll
            for (int g = 0; g < NB; g++)
#pragma unroll
                for (int mi = 0; mi < MI; mi++)
#pragma unroll
                    for (int ni = 0; ni < NMMA; ni++)
                        mma16816(acc[g][mi][ni], a[mi], &b[g][ni >> 1][(ni & 1) * 2]);
        }
        __syncthreads();
    }

    // ---- epilogue ----
    const float s0 = *s0p;
    const float s1 = *s1p;
    if (NB == 2) {
        __half* out = (__half*)outp;
#pragma unroll
        for (int mi = 0; mi < MI; mi++)
#pragma unroll
            for (int ni = 0; ni < NMMA; ni++) {
                int row0 = mt * BM + wm * 64 + mi * 16 + (lane >> 2);
                int col  = nt * BN_EACH + wn * WN_COLS + ni * 8 + (lane & 3) * 2;
#pragma unroll
                for (int h = 0; h < 2; h++) {
                    int row = row0 + h * 8;
                    float g0 = s0 * acc[0][mi][ni][2 * h + 0];
                    float g1 = s0 * acc[0][mi][ni][2 * h + 1];
                    float u0 = s1 * acc[1][mi][ni][2 * h + 0];
                    float u1 = s1 * acc[1][mi][ni][2 * h + 1];
                    float r0 = g0 / (1.f + __expf(-g0)) * u0;
                    float r1 = g1 / (1.f + __expf(-g1)) * u1;
                    *(__half2*)(out + (size_t)row * ncols + col) =
                        __floats2half2_rn(r0, r1);
                }
            }
    } else {
        float* out = (float*)outp;
#pragma unroll
        for (int mi = 0; mi < MI; mi++)
#pragma unroll
            for (int ni = 0; ni < NMMA; ni++) {
                int row0 = mt * BM + wm * 64 + mi * 16 + (lane >> 2);
                int col  = nt * BN_EACH + wn * WN_COLS + ni * 8 + (lane & 3) * 2;
#pragma unroll
                for (int h = 0; h < 2; h++) {
                    int row = row0 + h * 8;
                    float2 v;
                    v.x = s0 * acc[0][mi][ni][2 * h + 0];
                    v.y = s0 * acc[0][mi][ni][2 * h + 1];
                    *(float2*)(out + (size_t)row * ncols + col) = v;
                }
            }
    }
}

// ============================================================================
// Host side
// ============================================================================
extern "C" void kernel_launch(void* const* d_in, const int* in_sizes, int n_in,
                              void* d_out, int out_size) {
    const float* x  = (const float*)d_in[0];
    const int*   wg = (const int*)d_in[1];
    const int*   wu = (const int*)d_in[2];
    const int*   wd = (const int*)d_in[3];
    const float* sg = (const float*)d_in[4];
    const float* su = (const float*)d_in[5];
    const float* sd = (const float*)d_in[6];

    void *px, *pwg, *pwu, *pwd, *pmid;
    cudaGetSymbolAddress(&px,  g_x);
    cudaGetSymbolAddress(&pwg, g_wg);
    cudaGetSymbolAddress(&pwu, g_wu);
    cudaGetSymbolAddress(&pwd, g_wd);
    cudaGetSymbolAddress(&pmid, g_mid);

    // --- dequant / convert ---
    {
        int n8x = (MROWS * DIMN) / 8;
        cvt_f32_to_h<<<n8x / 256, 256>>>((const float4*)x, (uint4*)px, n8x);
        int n8w = (HID * DIMN) / 8;
        cvt_i32_to_h<<<n8w / 256, 256>>>((const int4*)wg, (uint4*)pwg, n8w);
        cvt_i32_to_h<<<n8w / 256, 256>>>((const int4*)wu, (uint4*)pwu, n8w);
        cvt_i32_to_h<<<n8w / 256, 256>>>((const int4*)wd, (uint4*)pwd, n8w);
    }

    constexpr int STAGES = 4;
    constexpr int SMEM_BYTES = STAGES * 49152;   // 196608
    cudaFuncSetAttribute(ffn_gemm<2, 128, STAGES>,
                         cudaFuncAttributeMaxDynamicSharedMemorySize, SMEM_BYTES);
    cudaFuncSetAttribute(ffn_gemm<1, 256, STAGES>,
                         cudaFuncAttributeMaxDynamicSharedMemorySize, SMEM_BYTES);

    // GEMM1: fused gate+up+SwiGLU -> g_mid (fp16).  C tile: 128 x 128 (x2 mats)
    {
        int mtiles = MROWS / 128;   // 64
        int ntiles = HID / 128;     // 86
        ffn_gemm<2, 128, STAGES><<<mtiles * ntiles, 256, SMEM_BYTES>>>(
            (const __half*)px, (const __half*)pwg, (const __half*)pwu,
            pmid, sg, su, DIMN, ntiles, HID);
    }
    // GEMM2: down projection -> d_out (fp32).  C tile: 128 x 256
    {
        int mtiles = MROWS / 128;   // 64
        int ntiles = DIMN / 256;    // 16
        ffn_gemm<1, 256, STAGES><<<mtiles * ntiles, 256, SMEM_BYTES>>>(
            (const __half*)pmid, (const __half*)pwd, (const __half*)pwd,
            d_out, sd, sd, HID, ntiles, DIMN);
    }
}

// round 4
// speedup vs baseline: 1.2472x; 1.0192x over previous
#include <cuda_runtime.h>
#include <cuda_fp16.h>
#include <cstdint>

// ============================================================================
// Problem sizes (fixed for this dataset)
// ============================================================================
static constexpr int DIMN  = 4096;
static constexpr int HID   = 11008;
static constexpr int MROWS = 8192;   // B*S = 4*2048

// ============================================================================
// Device scratch (allocation-free rule: __device__ globals)
// ============================================================================
static __device__ __align__(256) __half g_x  [(size_t)MROWS * DIMN];
static __device__ __align__(256) __half g_wg [(size_t)HID   * DIMN];
static __device__ __align__(256) __half g_wu [(size_t)HID   * DIMN];
static __device__ __align__(256) __half g_wd [(size_t)DIMN  * HID ];
static __device__ __align__(256) __half g_mid[(size_t)MROWS * HID ];

// ============================================================================
// PTX helpers — compute_103-safe only (cp.async, ldmatrix, mma.sync.m16n8k16)
// ============================================================================
__device__ __forceinline__ uint32_t smem_to_u32(const void* smem_ptr) {
    uint32_t addr;
    asm("{ .reg .u64 tmp; cvta.to.shared.u64 tmp, %1; cvt.u32.u64 %0, tmp; }"
        : "=r"(addr) : "l"(smem_ptr));
    return addr;
}

__device__ __forceinline__ void cp_async16(uint32_t dst, const void* src) {
    asm volatile("cp.async.cg.shared.global [%0], [%1], 16;\n"
                 :: "r"(dst), "l"(src) : "memory");
}
#define CP_COMMIT() asm volatile("cp.async.commit_group;\n" ::: "memory")
template <int N>
__device__ __forceinline__ void cp_wait() {
    asm volatile("cp.async.wait_group %0;\n" :: "n"(N) : "memory");
}

__device__ __forceinline__ void ldsm_x4(uint32_t& r0, uint32_t& r1,
                                        uint32_t& r2, uint32_t& r3, uint32_t addr) {
    asm volatile("ldmatrix.sync.aligned.m8n8.x4.shared.b16 {%0,%1,%2,%3}, [%4];"
                 : "=r"(r0), "=r"(r1), "=r"(r2), "=r"(r3) : "r"(addr));
}

__device__ __forceinline__ void mma16816(float* c, const uint32_t* a, const uint32_t* b) {
    asm volatile(
        "mma.sync.aligned.m16n8k16.row.col.f32.f16.f16.f32 "
        "{%0,%1,%2,%3}, {%4,%5,%6,%7}, {%8,%9}, {%0,%1,%2,%3};"
        : "+f"(c[0]), "+f"(c[1]), "+f"(c[2]), "+f"(c[3])
        : "r"(a[0]), "r"(a[1]), "r"(a[2]), "r"(a[3]), "r"(b[0]), "r"(b[1]));
}

// ============================================================================
// Merged dequant/convert: one launch covering x (f32->f16) and the three
// weights (i32->f16). Block ranges select the tensor.
// ============================================================================
static constexpr int N8X = (MROWS * DIMN) / 8;   // 4,194,304 -> 16384 blocks
static constexpr int N8W = (HID * DIMN) / 8;     // 5,636,096 -> 22016 blocks
static constexpr int BX  = N8X / 256;            // 16384
static constexpr int BW  = N8W / 256;            // 22016

__global__ void __launch_bounds__(256) cvt_all(
    const float4* __restrict__ x, const int4* __restrict__ wg,
    const int4* __restrict__ wu, const int4* __restrict__ wd,
    uint4* __restrict__ ox, uint4* __restrict__ owg,
    uint4* __restrict__ owu, uint4* __restrict__ owd)
{
    int b = blockIdx.x;
    if (b < BX) {
        int i = b * 256 + threadIdx.x;
        float4 a = x[2 * i];
        float4 c = x[2 * i + 1];
        __half2 h0 = __floats2half2_rn(a.x, a.y);
        __half2 h1 = __floats2half2_rn(a.z, a.w);
        __half2 h2 = __floats2half2_rn(c.x, c.y);
        __half2 h3 = __floats2half2_rn(c.z, c.w);
        uint4 r;
        r.x = *reinterpret_cast<uint32_t*>(&h0);
        r.y = *reinterpret_cast<uint32_t*>(&h1);
        r.z = *reinterpret_cast<uint32_t*>(&h2);
        r.w = *reinterpret_cast<uint32_t*>(&h3);
        ox[i] = r;
        return;
    }
    b -= BX;
    const int4* src;
    uint4* dst;
    if (b < BW)            { src = wg; dst = owg; }
    else if (b < 2 * BW)   { src = wu; dst = owu; b -= BW; }
    else                   { src = wd; dst = owd; b -= 2 * BW; }
    int i = b * 256 + threadIdx.x;
    int4 a = src[2 * i];
    int4 c = src[2 * i + 1];
    __half2 h0 = __halves2half2(__int2half_rn(a.x), __int2half_rn(a.y));
    __half2 h1 = __halves2half2(__int2half_rn(a.z), __int2half_rn(a.w));
    __half2 h2 = __halves2half2(__int2half_rn(c.x), __int2half_rn(c.y));
    __half2 h3 = __halves2half2(__int2half_rn(c.z), __int2half_rn(c.w));
    uint4 r;
    r.x = *reinterpret_cast<uint32_t*>(&h0);
    r.y = *reinterpret_cast<uint32_t*>(&h1);
    r.z = *reinterpret_cast<uint32_t*>(&h2);
    r.w = *reinterpret_cast<uint32_t*>(&h3);
    dst[i] = r;
}

// ============================================================================
// Multistage cp.async + mma.sync GEMM (C = A * B^T), fp16 in, fp32 accum.
//   NB==2 (BN_EACH=128): gate+up share A tile; fused SwiGLU -> fp16 mid.
//   NB==1 (BN_EACH=256): down proj; scaled fp32 out.
// CTA tile: 128(m) x 256(n-total) x 64(k). 256 threads = 8 warps as 2m x 4n.
// ONE __syncthreads per k-chunk: wait -> sync -> prefetch(kc+S-1) -> compute(kc)
// (prefetch writes slot (kc-1)%S, which the sync just proved fully consumed).
// SMEM rows 64 halves = 128B, XOR-swizzled: byte[6:4] ^= row[2:0].
// ============================================================================
template <int NB, int BN_EACH, int STAGES>
__global__ void __launch_bounds__(256, 1) ffn_gemm(
    const __half* __restrict__ A,
    const __half* __restrict__ B0,
    const __half* __restrict__ B1,
    void* __restrict__ outp,
    const float* __restrict__ s0p,
    const float* __restrict__ s1p,
    int K, int ntiles, int ncols)
{
    constexpr int BM = 128, BK = 64;
    constexpr int WN_COLS = BN_EACH / 4;          // warp n-slice per matrix
    constexpr int MI   = 4;                        // m16 groups per warp (64 rows)
    constexpr int NMMA = WN_COLS / 8;              // n8 mmas per warp per matrix
    constexpr int A_BYTES = BM * BK * 2;           // 16384
    constexpr int B_BYTES = BN_EACH * BK * 2;
    constexpr int STAGE_BYTES = A_BYTES + NB * B_BYTES;   // 49152
    constexpr int A_ITERS = (BM * 8) / 256;        // 4
    constexpr int B_ITERS = (BN_EACH * 8) / 256;   // 4 or 8

    extern __shared__ char smem[];
    const uint32_t sb = smem_to_u32(smem);

    const int tid  = threadIdx.x;
    const int wid  = tid >> 5;
    const int lane = tid & 31;
    const int wm   = wid & 1;       // 0..1 (m)
    const int wn   = wid >> 1;      // 0..3 (n)
    const int quad = lane >> 3;     // 0..3
    const int qr   = lane & 7;

    // L2-friendly tile mapping: groups of 8 m-tiles, n fastest within a group
    constexpr int GM = 8;
    const int tpg = GM * ntiles;
    const int grp = blockIdx.x / tpg;
    const int rem = blockIdx.x % tpg;
    const int mt  = grp * GM + (rem % GM);
    const int nt  = rem / GM;

    const int kch = K / BK;

    float acc[NB][MI][NMMA][4];
#pragma unroll
    for (int g = 0; g < NB; g++)
#pragma unroll
        for (int mi = 0; mi < MI; mi++)
#pragma unroll
            for (int ni = 0; ni < NMMA; ni++)
#pragma unroll
                for (int q = 0; q < 4; q++) acc[g][mi][ni][q] = 0.f;

    // ---- affine loader bases (row stride 32 keeps row&7, so swizzle fixed) --
    const int lrow = tid >> 3;                    // 0..31
    const int lch  = tid & 7;
    const uint32_t ldst = lrow * 128 + ((lch * 16) ^ ((lrow & 7) << 4));
    const __half* aP = A + (size_t)(mt * BM + lrow) * K + lch * 8;
    const __half* bP[2];
    bP[0] = B0 + (size_t)(nt * BN_EACH + lrow) * K + lch * 8;
    bP[1] = B1 + (size_t)(nt * BN_EACH + lrow) * K + lch * 8;
    const size_t rstep = (size_t)32 * K;          // 32 rows forward

    auto load_stage = [&](int kc, int slot) {
        const uint32_t st = sb + slot * STAGE_BYTES + ldst;
        const int k0 = kc * BK;
#pragma unroll
        for (int it = 0; it < A_ITERS; it++)
            cp_async16(st + it * 4096, aP + k0 + it * rstep);
#pragma unroll
        for (int g = 0; g < NB; g++) {
            const __half* bp = bP[g] + k0;
            const uint32_t bbase = st + A_BYTES + g * B_BYTES;
#pragma unroll
            for (int it = 0; it < B_ITERS; it++)
                cp_async16(bbase + it * 4096, bp + it * rstep);
        }
    };

    // ---- prologue: stages 0..S-2 ----
#pragma unroll
    for (int s = 0; s < STAGES - 1; s++) {
        load_stage(s, s);
        CP_COMMIT();
    }

    // ---- main loop: ONE sync per chunk ----
    for (int kc = 0; kc < kch; kc++) {
        cp_wait<STAGES - 2>();          // stage kc resident
        __syncthreads();                // all warps done reading slot (kc-1)%S

        const int pre = kc + STAGES - 1;
        if (pre < kch) load_stage(pre, pre % STAGES);
        CP_COMMIT();

        const uint32_t st = sb + (kc % STAGES) * STAGE_BYTES;
#pragma unroll
        for (int ks = 0; ks < 4; ks++) {
            uint32_t a[MI][4];
#pragma unroll
            for (int mi = 0; mi < MI; mi++) {
                int row  = wm * 64 + mi * 16 + (quad & 1) * 8 + qr;
                int colb = ks * 32 + (quad >> 1) * 16;
                uint32_t ad = st + row * 128 + (colb ^ ((row & 7) << 4));
                ldsm_x4(a[mi][0], a[mi][1], a[mi][2], a[mi][3], ad);
            }
            uint32_t b[NB][NMMA / 2][4];
#pragma unroll
            for (int g = 0; g < NB; g++)
#pragma unroll
                for (int j = 0; j < NMMA / 2; j++) {
                    int row  = wn * WN_COLS + j * 16 + (quad >> 1) * 8 + qr;
                    int colb = ks * 32 + (quad & 1) * 16;
                    uint32_t bd = st + A_BYTES + g * B_BYTES + row * 128 +
                                  (colb ^ ((row & 7) << 4));
                    ldsm_x4(b[g][j][0], b[g][j][1], b[g][j][2], b[g][j][3], bd);
                }
#pragma unroll
            for (int g = 0; g < NB; g++)
#pragma unroll
                for (int mi = 0; mi < MI; mi++)
#pragma unroll
                    for (int ni = 0; ni < NMMA; ni++)
                        mma16816(acc[g][mi][ni], a[mi], &b[g][ni >> 1][(ni & 1) * 2]);
        }
    }

    // ---- epilogue ----
    const float s0 = *s0p;
    const float s1 = *s1p;
    if (NB == 2) {
        __half* out = (__half*)outp;
#pragma unroll
        for (int mi = 0; mi < MI; mi++)
#pragma unroll
            for (int ni = 0; ni < NMMA; ni++) {
                int row0 = mt * BM + wm * 64 + mi * 16 + (lane >> 2);
                int col  = nt * BN_EACH + wn * WN_COLS + ni * 8 + (lane & 3) * 2;
#pragma unroll
                for (int h = 0; h < 2; h++) {
                    int row = row0 + h * 8;
                    float g0 = s0 * acc[0][mi][ni][2 * h + 0];
                    float g1 = s0 * acc[0][mi][ni][2 * h + 1];
                    float u0 = s1 * acc[1][mi][ni][2 * h + 0];
                    float u1 = s1 * acc[1][mi][ni][2 * h + 1];
                    float r0 = g0 / (1.f + __expf(-g0)) * u0;
                    float r1 = g1 / (1.f + __expf(-g1)) * u1;
                    *(__half2*)(out + (size_t)row * ncols + col) =
                        __floats2half2_rn(r0, r1);
                }
            }
    } else {
        float* out = (float*)outp;
#pragma unroll
        for (int mi = 0; mi < MI; mi++)
#pragma unroll
            for (int ni = 0; ni < NMMA; ni++) {
                int row0 = mt * BM + wm * 64 + mi * 16 + (lane >> 2);
                int col  = nt * BN_EACH + wn * WN_COLS + ni * 8 + (lane & 3) * 2;
#pragma unroll
                for (int h = 0; h < 2; h++) {
                    int row = row0 + h * 8;
                    float2 v;
                    v.x = s0 * acc[0][mi][ni][2 * h + 0];
                    v.y = s0 * acc[0][mi][ni][2 * h + 1];
                    *(float2*)(out + (size_t)row * ncols + col) = v;
                }
            }
    }
}

// ============================================================================
// Host side
// ============================================================================
extern "C" void kernel_launch(void* const* d_in, const int* in_sizes, int n_in,
                              void* d_out, int out_size) {
    const float* x  = (const float*)d_in[0];
    const int*   wg = (const int*)d_in[1];
    const int*   wu = (const int*)d_in[2];
    const int*   wd = (const int*)d_in[3];
    const float* sg = (const float*)d_in[4];
    const float* su = (const float*)d_in[5];
    const float* sd = (const float*)d_in[6];

    void *px, *pwg, *pwu, *pwd, *pmid;
    cudaGetSymbolAddress(&px,  g_x);
    cudaGetSymbolAddress(&pwg, g_wg);
    cudaGetSymbolAddress(&pwu, g_wu);
    cudaGetSymbolAddress(&pwd, g_wd);
    cudaGetSymbolAddress(&pmid, g_mid);

    // --- merged dequant / convert (one launch) ---
    cvt_all<<<BX + 3 * BW, 256>>>(
        (const float4*)x, (const int4*)wg, (const int4*)wu, (const int4*)wd,
        (uint4*)px, (uint4*)pwg, (uint4*)pwu, (uint4*)pwd);

    constexpr int STAGES = 4;
    constexpr int SMEM_BYTES = STAGES * 49152;   // 196608
    cudaFuncSetAttribute(ffn_gemm<2, 128, STAGES>,
                         cudaFuncAttributeMaxDynamicSharedMemorySize, SMEM_BYTES);
    cudaFuncSetAttribute(ffn_gemm<1, 256, STAGES>,
                         cudaFuncAttributeMaxDynamicSharedMemorySize, SMEM_BYTES);

    // GEMM1: fused gate+up+SwiGLU -> g_mid (fp16).  C tile: 128 x 128 (x2 mats)
    {
        int mtiles = MROWS / 128;   // 64
        int ntiles = HID / 128;     // 86
        ffn_gemm<2, 128, STAGES><<<mtiles * ntiles, 256, SMEM_BYTES>>>(
            (const __half*)px, (const __half*)pwg, (const __half*)pwu,
            pmid, sg, su, DIMN, ntiles, HID);
    }
    // GEMM2: down projection -> d_out (fp32).  C tile: 128 x 256
    {
        int mtiles = MROWS / 128;   // 64
        int ntiles = DIMN / 256;    // 16
        ffn_gemm<1, 256, STAGES><<<mtiles * ntiles, 256, SMEM_BYTES>>>(
            (const __half*)pmid, (const __half*)pwd, (const __half*)pwd,
            d_out, sd, sd, HID, ntiles, DIMN);
    }
}

// round 5
// speedup vs baseline: 1.2500x; 1.0023x over previous
#include <cuda_runtime.h>
#include <cuda_fp16.h>
#include <cstdint>

// ============================================================================
// Problem sizes (fixed for this dataset)
// ============================================================================
static constexpr int DIMN  = 4096;
static constexpr int HID   = 11008;
static constexpr int MROWS = 8192;   // B*S = 4*2048

// ============================================================================
// Device scratch (allocation-free rule: __device__ globals)
// ============================================================================
static __device__ __align__(256) __half g_x  [(size_t)MROWS * DIMN];
static __device__ __align__(256) __half g_wg [(size_t)HID   * DIMN];
static __device__ __align__(256) __half g_wu [(size_t)HID   * DIMN];
static __device__ __align__(256) __half g_wd [(size_t)DIMN  * HID ];
static __device__ __align__(256) __half g_mid[(size_t)MROWS * HID ];

// ============================================================================
// PTX helpers — compute_103-safe only (cp.async, ldmatrix, mma.sync.m16n8k16)
// ============================================================================
__device__ __forceinline__ uint32_t smem_to_u32(const void* smem_ptr) {
    uint32_t addr;
    asm("{ .reg .u64 tmp; cvta.to.shared.u64 tmp, %1; cvt.u32.u64 %0, tmp; }"
        : "=r"(addr) : "l"(smem_ptr));
    return addr;
}

__device__ __forceinline__ void cp_async16(uint32_t dst, const void* src) {
    asm volatile("cp.async.cg.shared.global [%0], [%1], 16;\n"
                 :: "r"(dst), "l"(src) : "memory");
}
#define CP_COMMIT() asm volatile("cp.async.commit_group;\n" ::: "memory")
template <int N>
__device__ __forceinline__ void cp_wait() {
    asm volatile("cp.async.wait_group %0;\n" :: "n"(N) : "memory");
}

__device__ __forceinline__ void ldsm_x4(uint32_t& r0, uint32_t& r1,
                                        uint32_t& r2, uint32_t& r3, uint32_t addr) {
    asm volatile("ldmatrix.sync.aligned.m8n8.x4.shared.b16 {%0,%1,%2,%3}, [%4];"
                 : "=r"(r0), "=r"(r1), "=r"(r2), "=r"(r3) : "r"(addr));
}

__device__ __forceinline__ void mma16816(float* c, const uint32_t* a, const uint32_t* b) {
    asm volatile(
        "mma.sync.aligned.m16n8k16.row.col.f32.f16.f16.f32 "
        "{%0,%1,%2,%3}, {%4,%5,%6,%7}, {%8,%9}, {%0,%1,%2,%3};"
        : "+f"(c[0]), "+f"(c[1]), "+f"(c[2]), "+f"(c[3])
        : "r"(a[0]), "r"(a[1]), "r"(a[2]), "r"(a[3]), "r"(b[0]), "r"(b[1]));
}

// ============================================================================
// Merged dequant/convert: one launch covering x (f32->f16) and the three
// weights (i32->f16). Block ranges select the tensor.
// ============================================================================
static constexpr int N8X = (MROWS * DIMN) / 8;   // 4,194,304 -> 16384 blocks
static constexpr int N8W = (HID * DIMN) / 8;     // 5,636,096 -> 22016 blocks
static constexpr int BX  = N8X / 256;            // 16384
static constexpr int BW  = N8W / 256;            // 22016

__global__ void __launch_bounds__(256) cvt_all(
    const float4* __restrict__ x, const int4* __restrict__ wg,
    const int4* __restrict__ wu, const int4* __restrict__ wd,
    uint4* __restrict__ ox, uint4* __restrict__ owg,
    uint4* __restrict__ owu, uint4* __restrict__ owd)
{
    int b = blockIdx.x;
    if (b < BX) {
        int i = b * 256 + threadIdx.x;
        float4 a = x[2 * i];
        float4 c = x[2 * i + 1];
        __half2 h0 = __floats2half2_rn(a.x, a.y);
        __half2 h1 = __floats2half2_rn(a.z, a.w);
        __half2 h2 = __floats2half2_rn(c.x, c.y);
        __half2 h3 = __floats2half2_rn(c.z, c.w);
        uint4 r;
        r.x = *reinterpret_cast<uint32_t*>(&h0);
        r.y = *reinterpret_cast<uint32_t*>(&h1);
        r.z = *reinterpret_cast<uint32_t*>(&h2);
        r.w = *reinterpret_cast<uint32_t*>(&h3);
        ox[i] = r;
        return;
    }
    b -= BX;
    const int4* src;
    uint4* dst;
    if (b < BW)            { src = wg; dst = owg; }
    else if (b < 2 * BW)   { src = wu; dst = owu; b -= BW; }
    else                   { src = wd; dst = owd; b -= 2 * BW; }
    int i = b * 256 + threadIdx.x;
    int4 a = src[2 * i];
    int4 c = src[2 * i + 1];
    __half2 h0 = __halves2half2(__int2half_rn(a.x), __int2half_rn(a.y));
    __half2 h1 = __halves2half2(__int2half_rn(a.z), __int2half_rn(a.w));
    __half2 h2 = __halves2half2(__int2half_rn(c.x), __int2half_rn(c.y));
    __half2 h3 = __halves2half2(__int2half_rn(c.z), __int2half_rn(c.w));
    uint4 r;
    r.x = *reinterpret_cast<uint32_t*>(&h0);
    r.y = *reinterpret_cast<uint32_t*>(&h1);
    r.z = *reinterpret_cast<uint32_t*>(&h2);
    r.w = *reinterpret_cast<uint32_t*>(&h3);
    dst[i] = r;
}

// ============================================================================
// Multistage cp.async + mma.sync GEMM (C = A * B^T), fp16 in, fp32 accum.
//   NB==2 (BN_EACH=128): gate+up share A tile; fused SwiGLU -> fp16 mid.
//   NB==1 (BN_EACH=256): down proj; scaled fp32 out.
// CTA tile: 128(m) x 256(n-total) x 64(k). 256 threads = 8 warps as 2m x 4n.
// Chunk schedule: sync -> issue prefetch(kc+S-1) -> commit -> wait<S-1> ->
// compute, with intra-chunk fragment double buffering (ldsm ks+1 || mma ks)
// to hide LDSM latency at occupancy 1.
// SMEM rows 64 halves = 128B, XOR-swizzled: byte[6:4] ^= row[2:0].
// ============================================================================
template <int NB, int BN_EACH, int STAGES>
__global__ void __launch_bounds__(256, 1) ffn_gemm(
    const __half* __restrict__ A,
    const __half* __restrict__ B0,
    const __half* __restrict__ B1,
    void* __restrict__ outp,
    const float* __restrict__ s0p,
    const float* __restrict__ s1p,
    int K, int ntiles, int ncols)
{
    constexpr int BM = 128, BK = 64;
    constexpr int WN_COLS = BN_EACH / 4;          // warp n-slice per matrix
    constexpr int MI   = 4;                        // m16 groups per warp (64 rows)
    constexpr int NMMA = WN_COLS / 8;              // n8 mmas per warp per matrix
    constexpr int NJ   = NB * (NMMA / 2);          // n16 ldsm groups total (4)
    constexpr int A_BYTES = BM * BK * 2;           // 16384
    constexpr int B_BYTES = BN_EACH * BK * 2;
    constexpr int STAGE_BYTES = A_BYTES + NB * B_BYTES;   // 49152
    constexpr int A_ITERS = (BM * 8) / 256;        // 4
    constexpr int B_ITERS = (BN_EACH * 8) / 256;   // 4 or 8

    extern __shared__ char smem[];
    const uint32_t sb = smem_to_u32(smem);

    const int tid  = threadIdx.x;
    const int wid  = tid >> 5;
    const int lane = tid & 31;
    const int wm   = wid & 1;       // 0..1 (m)
    const int wn   = wid >> 1;      // 0..3 (n)
    const int quad = lane >> 3;     // 0..3
    const int qr   = lane & 7;

    // L2-friendly tile mapping: groups of 8 m-tiles, n fastest within a group
    constexpr int GM = 8;
    const int tpg = GM * ntiles;
    const int grp = blockIdx.x / tpg;
    const int rem = blockIdx.x % tpg;
    const int mt  = grp * GM + (rem % GM);
    const int nt  = rem / GM;

    const int kch = K / BK;

    float acc[NB][MI][NMMA][4];
#pragma unroll
    for (int g = 0; g < NB; g++)
#pragma unroll
        for (int mi = 0; mi < MI; mi++)
#pragma unroll
            for (int ni = 0; ni < NMMA; ni++)
#pragma unroll
                for (int q = 0; q < 4; q++) acc[g][mi][ni][q] = 0.f;

    // ---- affine loader bases (row stride 32 keeps row&7, so swizzle fixed) --
    const int lrow = tid >> 3;                    // 0..31
    const int lch  = tid & 7;
    const uint32_t ldst = lrow * 128 + ((lch * 16) ^ ((lrow & 7) << 4));
    const __half* aP = A + (size_t)(mt * BM + lrow) * K + lch * 8;
    const __half* bP[2];
    bP[0] = B0 + (size_t)(nt * BN_EACH + lrow) * K + lch * 8;
    bP[1] = B1 + (size_t)(nt * BN_EACH + lrow) * K + lch * 8;
    const size_t rstep = (size_t)32 * K;          // 32 rows forward

    auto load_stage = [&](int kc, int slot) {
        const uint32_t st = sb + slot * STAGE_BYTES + ldst;
        const int k0 = kc * BK;
#pragma unroll
        for (int it = 0; it < A_ITERS; it++)
            cp_async16(st + it * 4096, aP + k0 + it * rstep);
#pragma unroll
        for (int g = 0; g < NB; g++) {
            const __half* bp = bP[g] + k0;
            const uint32_t bbase = st + A_BYTES + g * B_BYTES;
#pragma unroll
            for (int it = 0; it < B_ITERS; it++)
                cp_async16(bbase + it * 4096, bp + it * rstep);
        }
    };

    // ---- ldsm address components (row part fixed per thread) ----
    // A: row = wm*64 + mi*16 + (quad&1)*8 + qr ; col byte = ks*32 + (quad>>1)*16
    uint32_t aRow[MI], aXor;
#pragma unroll
    for (int mi = 0; mi < MI; mi++) {
        int row = wm * 64 + mi * 16 + (quad & 1) * 8 + qr;
        aRow[mi] = row * 128 + (((quad >> 1) * 16) ^ ((row & 7) << 4)) -
                   (((quad >> 1) * 16));   // keep xor folded via recompute below
    }
    (void)aXor;
    // B: row = wn*WN_COLS + j16*16 + (quad>>1)*8 + qr ; col byte = ks*32 + (quad&1)*16

    // fragment double buffers
    uint32_t fa[2][MI][4];
    uint32_t fb[2][NJ][4];

    auto ldsm_frags = [&](uint32_t st, int ks, int buf) {
#pragma unroll
        for (int mi = 0; mi < MI; mi++) {
            int row  = wm * 64 + mi * 16 + (quad & 1) * 8 + qr;
            int colb = ks * 32 + (quad >> 1) * 16;
            uint32_t ad = st + row * 128 + (colb ^ ((row & 7) << 4));
            ldsm_x4(fa[buf][mi][0], fa[buf][mi][1], fa[buf][mi][2], fa[buf][mi][3], ad);
        }
#pragma unroll
        for (int g = 0; g < NB; g++)
#pragma unroll
            for (int j = 0; j < NMMA / 2; j++) {
                int row  = wn * WN_COLS + j * 16 + (quad >> 1) * 8 + qr;
                int colb = ks * 32 + (quad & 1) * 16;
                uint32_t bd = st + A_BYTES + g * B_BYTES + row * 128 +
                              (colb ^ ((row & 7) << 4));
                int jj = g * (NMMA / 2) + j;
                ldsm_x4(fb[buf][jj][0], fb[buf][jj][1], fb[buf][jj][2], fb[buf][jj][3], bd);
            }
    };

    auto mma_frags = [&](int buf) {
#pragma unroll
        for (int g = 0; g < NB; g++)
#pragma unroll
            for (int mi = 0; mi < MI; mi++)
#pragma unroll
                for (int ni = 0; ni < NMMA; ni++)
                    mma16816(acc[g][mi][ni], fa[buf][mi],
                             &fb[buf][g * (NMMA / 2) + (ni >> 1)][(ni & 1) * 2]);
    };

    // ---- prologue: stages 0..S-2 ----
#pragma unroll
    for (int s = 0; s < STAGES - 1; s++) {
        load_stage(s, s);
        CP_COMMIT();
    }

    // ---- main loop ----
    for (int kc = 0; kc < kch; kc++) {
        __syncthreads();                 // all warps done reading slot (kc-1)%S
        const int pre = kc + STAGES - 1;
        if (pre < kch) load_stage(pre, pre % STAGES);
        CP_COMMIT();
        cp_wait<STAGES - 1>();           // stage kc resident (prefetch overlapped)
        __syncthreads();                 // stage-kc data visible to all warps

        const uint32_t st = sb + (kc % STAGES) * STAGE_BYTES;
        ldsm_frags(st, 0, 0);
#pragma unroll
        for (int ks = 0; ks < 4; ks++) {
            if (ks < 3) ldsm_frags(st, ks + 1, (ks + 1) & 1);
            mma_frags(ks & 1);
        }
    }

    // ---- epilogue ----
    const float s0 = *s0p;
    const float s1 = *s1p;
    if (NB == 2) {
        __half* out = (__half*)outp;
#pragma unroll
        for (int mi = 0; mi < MI; mi++)
#pragma unroll
            for (int ni = 0; ni < NMMA; ni++) {
                int row0 = mt * BM + wm * 64 + mi * 16 + (lane >> 2);
                int col  = nt * BN_EACH + wn * WN_COLS + ni * 8 + (lane & 3) * 2;
#pragma unroll
                for (int h = 0; h < 2; h++) {
                    int row = row0 + h * 8;
                    float g0 = s0 * acc[0][mi][ni][2 * h + 0];
                    float g1 = s0 * acc[0][mi][ni][2 * h + 1];
                    float u0 = s1 * acc[1][mi][ni][2 * h + 0];
                    float u1 = s1 * acc[1][mi][ni][2 * h + 1];
                    float r0 = g0 / (1.f + __expf(-g0)) * u0;
                    float r1 = g1 / (1.f + __expf(-g1)) * u1;
                    *(__half2*)(out + (size_t)row * ncols + col) =
                        __floats2half2_rn(r0, r1);
                }
            }
    } else {
        float* out = (float*)outp;
#pragma unroll
        for (int mi = 0; mi < MI; mi++)
#pragma unroll
            for (int ni = 0; ni < NMMA; ni++) {
                int row0 = mt * BM + wm * 64 + mi * 16 + (lane >> 2);
                int col  = nt * BN_EACH + wn * WN_COLS + ni * 8 + (lane & 3) * 2;
#pragma unroll
                for (int h = 0; h < 2; h++) {
                    int row = row0 + h * 8;
                    float2 v;
                    v.x = s0 * acc[0][mi][ni][2 * h + 0];
                    v.y = s0 * acc[0][mi][ni][2 * h + 1];
                    *(float2*)(out + (size_t)row * ncols + col) = v;
                }
            }
    }
}

// ============================================================================
// Host side
// ============================================================================
extern "C" void kernel_launch(void* const* d_in, const int* in_sizes, int n_in,
                              void* d_out, int out_size) {
    const float* x  = (const float*)d_in[0];
    const int*   wg = (const int*)d_in[1];
    const int*   wu = (const int*)d_in[2];
    const int*   wd = (const int*)d_in[3];
    const float* sg = (const float*)d_in[4];
    const float* su = (const float*)d_in[5];
    const float* sd = (const float*)d_in[6];

    void *px, *pwg, *pwu, *pwd, *pmid;
    cudaGetSymbolAddress(&px,  g_x);
    cudaGetSymbolAddress(&pwg, g_wg);
    cudaGetSymbolAddress(&pwu, g_wu);
    cudaGetSymbolAddress(&pwd, g_wd);
    cudaGetSymbolAddress(&pmid, g_mid);

    // --- merged dequant / convert (one launch) ---
    cvt_all<<<BX + 3 * BW, 256>>>(
        (const float4*)x, (const int4*)wg, (const int4*)wu, (const int4*)wd,
        (uint4*)px, (uint4*)pwg, (uint4*)pwu, (uint4*)pwd);

    constexpr int STAGES = 4;
    constexpr int SMEM_BYTES = STAGES * 49152;   // 196608
    cudaFuncSetAttribute(ffn_gemm<2, 128, STAGES>,
                         cudaFuncAttributeMaxDynamicSharedMemorySize, SMEM_BYTES);
    cudaFuncSetAttribute(ffn_gemm<1, 256, STAGES>,
                         cudaFuncAttributeMaxDynamicSharedMemorySize, SMEM_BYTES);

    // GEMM1: fused gate+up+SwiGLU -> g_mid (fp16).  C tile: 128 x 128 (x2 mats)
    {
        int mtiles = MROWS / 128;   // 64
        int ntiles = HID / 128;     // 86
        ffn_gemm<2, 128, STAGES><<<mtiles * ntiles, 256, SMEM_BYTES>>>(
            (const __half*)px, (const __half*)pwg, (const __half*)pwu,
            pmid, sg, su, DIMN, ntiles, HID);
    }
    // GEMM2: down projection -> d_out (fp32).  C tile: 128 x 256
    {
        int mtiles = MROWS / 128;   // 64
        int ntiles = DIMN / 256;    // 16
        ffn_gemm<1, 256, STAGES><<<mtiles * ntiles, 256, SMEM_BYTES>>>(
            (const __half*)pmid, (const __half*)pwd, (const __half*)pwd,
            d_out, sd, sd, HID, ntiles, DIMN);
    }
}